// round 1
// baseline (speedup 1.0000x reference)
#include <cuda_runtime.h>
#include <cuda_bf16.h>
#include <cstdint>

// ---------------------------------------------------------------------------
// BiLSTM: B=32, T=512, D=512, H=512. out = [B,T,2H] fp32.
// Phase 1: xg[dir][t][g][b] = x @ W_ih^T + b_ih + b_hh   (SGEMM, parallel)
// Phase 2: persistent recurrent scan with custom grid barrier (128 blocks)
// ---------------------------------------------------------------------------

#define B_  32
#define T_  512
#define D_  512
#define H_  512
#define G4  2048          // 4*H
#define NB  128           // persistent blocks in scan kernel

// Scratch (device globals: allocation-free rule)
__device__ float g_xg[2][T_][G4][B_];      // 268 MB, [dir][t][gate*H+j][b]
__device__ float g_h[2][2][H_][B_];        // [buf][dir][j][b]
__device__ volatile unsigned g_bar;

// ---------------------------------------------------------------------------
// Init: zero h state + barrier counter (must run every launch)
// ---------------------------------------------------------------------------
__global__ void init_kernel() {
    int idx = blockIdx.x * blockDim.x + threadIdx.x;
    if (idx == 0) *(unsigned*)&g_bar = 0u;
    float* p = &g_h[0][0][0][0];
    if (idx < 2 * 2 * H_ * B_) p[idx] = 0.f;
}

// ---------------------------------------------------------------------------
// Phase 1: C[M=16384, N=4096] = X[16384,512] * W^T, W row-major [N,K]
// 128x128 tile, K-chunk 8, 256 threads, 8x8 micro-tile.
// Epilogue adds (b_ih + b_hh) and scatters into g_xg[dir][t][g][b].
// ---------------------------------------------------------------------------
__global__ __launch_bounds__(256) void proj_kernel(
    const float* __restrict__ x,
    const float* __restrict__ Wf, const float* __restrict__ Wb,
    const float* __restrict__ bihf, const float* __restrict__ bhhf,
    const float* __restrict__ bihb, const float* __restrict__ bhhb)
{
    __shared__ __align__(16) float As[8][128];
    __shared__ __align__(16) float Bs[8][128];

    const int tid = threadIdx.x;
    const int tx  = tid & 15;        // n micro index
    const int ty  = tid >> 4;        // m micro index
    const int m0  = blockIdx.y * 128;
    const int n0  = blockIdx.x * 128;
    const int dir = n0 >> 11;        // 2048-column halves
    const int ng0 = n0 & 2047;
    const float* W   = dir ? Wb : Wf;
    const float* bih = dir ? bihb : bihf;
    const float* bhh = dir ? bhhb : bhhf;

    const int la_m = tid >> 1;           // 0..127
    const int la_k = (tid & 1) << 2;     // 0 or 4

    const float* Aptr = x + (size_t)(m0 + la_m) * D_ + la_k;
    const float* Bptr = W + (size_t)(ng0 + la_m) * D_ + la_k;

    float acc[8][8];
#pragma unroll
    for (int i = 0; i < 8; i++)
#pragma unroll
        for (int j = 0; j < 8; j++) acc[i][j] = 0.f;

    for (int k0 = 0; k0 < D_; k0 += 8) {
        float4 av = *(const float4*)(Aptr + k0);
        float4 bv = *(const float4*)(Bptr + k0);
        As[la_k + 0][la_m] = av.x; As[la_k + 1][la_m] = av.y;
        As[la_k + 2][la_m] = av.z; As[la_k + 3][la_m] = av.w;
        Bs[la_k + 0][la_m] = bv.x; Bs[la_k + 1][la_m] = bv.y;
        Bs[la_k + 2][la_m] = bv.z; Bs[la_k + 3][la_m] = bv.w;
        __syncthreads();
#pragma unroll
        for (int kk = 0; kk < 8; kk++) {
            float4 a0 = *(const float4*)&As[kk][ty * 8];
            float4 a1 = *(const float4*)&As[kk][ty * 8 + 4];
            float4 b0 = *(const float4*)&Bs[kk][tx * 8];
            float4 b1 = *(const float4*)&Bs[kk][tx * 8 + 4];
            float a[8] = {a0.x, a0.y, a0.z, a0.w, a1.x, a1.y, a1.z, a1.w};
            float bb[8] = {b0.x, b0.y, b0.z, b0.w, b1.x, b1.y, b1.z, b1.w};
#pragma unroll
            for (int i = 0; i < 8; i++)
#pragma unroll
                for (int j = 0; j < 8; j++)
                    acc[i][j] = fmaf(a[i], bb[j], acc[i][j]);
        }
        __syncthreads();
    }

#pragma unroll
    for (int j = 0; j < 8; j++) {
        int gcol = ng0 + tx * 8 + j;
        float bias = bih[gcol] + bhh[gcol];
#pragma unroll
        for (int i = 0; i < 8; i++) {
            int m = m0 + ty * 8 + i;
            int bb_ = m >> 9;       // batch
            int t   = m & 511;      // time
            g_xg[dir][t][gcol][bb_] = acc[i][j] + bias;
        }
    }
}

// ---------------------------------------------------------------------------
// Grid barrier (all NB blocks co-resident; fenced monotonic counter)
// ---------------------------------------------------------------------------
__device__ __forceinline__ void grid_sync(unsigned target) {
    __threadfence();
    __syncthreads();
    if (threadIdx.x == 0) {
        atomicAdd((unsigned*)&g_bar, 1u);
        while (g_bar < target) { }
        __threadfence();
    }
    __syncthreads();
}

// ---------------------------------------------------------------------------
// Phase 2: persistent recurrent scan.
// 128 blocks = 2 dirs x 64 j-tiles(8). 256 threads = 8 j x 32 b.
// W_hh slice cached in SMEM once; h double-buffered in global via L2 (cg ops).
// ---------------------------------------------------------------------------
__global__ __launch_bounds__(256, 1) void lstm_scan_kernel(
    const int*   __restrict__ lengths,
    const float* __restrict__ Whf,
    const float* __restrict__ Whb,
    float*       __restrict__ out)
{
    extern __shared__ float smem[];
    float* W_s = smem;            // 16384 floats: [jl][k][gate4]
    float* h_s = smem + 16384;    // 16384 floats: [k][b]

    const int tid = threadIdx.x;
    const int b   = tid & 31;
    const int jl  = tid >> 5;               // 0..7
    const int bx  = blockIdx.x;
    const int dir = bx >> 6;
    const int j0  = (bx & 63) << 3;
    const int jglob = j0 + jl;
    const float* W = dir ? Whb : Whf;

    // Fill W_s once: W_s[(jj*512 + k)*4 + gate] = W[(gate*512 + j0+jj)*512 + k]
    for (int idx = tid; idx < 8 * 4 * 512; idx += 256) {
        int jj   = idx >> 11;
        int rem  = idx & 2047;
        int gate = rem >> 9;
        int k    = rem & 511;
        W_s[(((jj << 9) + k) << 2) + gate] = W[(((gate << 9) + j0 + jj) << 9) + k];
    }

    const int len = lengths[b];
    float h_reg = 0.f, c_reg = 0.f;
    int cur = 0;
    const float4* Wp = (const float4*)W_s + (jl << 9);
    unsigned target = 0;

    for (int s = 0; s < T_; s++) {
        target += NB;
        grid_sync(target);   // prev-step h visible; also guards W_s fill (s=0) and h_s reuse

        // load h (L2, bypass L1 — custom barrier doesn't invalidate L1)
        const float4* hg = (const float4*)&g_h[cur][dir][0][0];
        float4* hs4 = (float4*)h_s;
#pragma unroll
        for (int i = 0; i < 16; i++)
            hs4[tid + (i << 8)] = __ldcg(hg + tid + (i << 8));
        __syncthreads();

        const int t = dir ? (T_ - 1 - s) : s;

        // prefetch gate pre-activations (DRAM latency hidden behind dot loop)
        const float* xgp = &g_xg[dir][t][0][0];
        float xi = xgp[((0 << 9) + jglob) * 32 + b];
        float xf = xgp[((1 << 9) + jglob) * 32 + b];
        float xgv = xgp[((2 << 9) + jglob) * 32 + b];
        float xo = xgp[((3 << 9) + jglob) * 32 + b];

        float4 acc = make_float4(0.f, 0.f, 0.f, 0.f);
#pragma unroll 8
        for (int k = 0; k < H_; k++) {
            float hv = h_s[(k << 5) + b];       // conflict-free (lane = b)
            float4 w = Wp[k];                   // LDS.128 broadcast
            acc.x = fmaf(hv, w.x, acc.x);
            acc.y = fmaf(hv, w.y, acc.y);
            acc.z = fmaf(hv, w.z, acc.z);
            acc.w = fmaf(hv, w.w, acc.w);
        }

        float ig = 1.f / (1.f + expf(-(acc.x + xi)));
        float fg = 1.f / (1.f + expf(-(acc.y + xf)));
        float gg = tanhf(acc.z + xgv);
        float og = 1.f / (1.f + expf(-(acc.w + xo)));
        float c_new = fg * c_reg + ig * gg;
        float h_new = og * tanhf(c_new);
        if (t < len) { c_reg = c_new; h_reg = h_new; }   // mask: hold state

        __stcg(&g_h[cur ^ 1][dir][jglob][b], h_reg);
        out[((size_t)b * T_ + t) * (2 * H_) + (dir << 9) + jglob] = h_reg;
        cur ^= 1;
    }
}

// ---------------------------------------------------------------------------
extern "C" void kernel_launch(void* const* d_in, const int* in_sizes, int n_in,
                              void* d_out, int out_size)
{
    const float* x      = (const float*)d_in[0];
    const int*   lens   = (const int*)  d_in[1];
    const float* Wihf   = (const float*)d_in[2];
    const float* Whhf   = (const float*)d_in[3];
    const float* bihf   = (const float*)d_in[4];
    const float* bhhf   = (const float*)d_in[5];
    const float* Wihb   = (const float*)d_in[6];
    const float* Whhb   = (const float*)d_in[7];
    const float* bihb   = (const float*)d_in[8];
    const float* bhhb   = (const float*)d_in[9];
    float* out = (float*)d_out;

    cudaFuncSetAttribute(lstm_scan_kernel,
                         cudaFuncAttributeMaxDynamicSharedMemorySize, 131072);

    init_kernel<<<256, 256>>>();

    dim3 pg(4096 / 128, 16384 / 128);   // (N tiles, M tiles)
    proj_kernel<<<pg, 256>>>(x, Wihf, Wihb, bihf, bhhf, bihb, bhhb);

    lstm_scan_kernel<<<NB, 256, 131072>>>(lens, Whhf, Whhb, out);
}